// round 12
// baseline (speedup 1.0000x reference)
#include <cuda_runtime.h>
#include <math.h>

#define Bn   32
#define Sn   1024
#define En   128
#define Hn   512
#define Gn   2048
#define Mn   32768
#define NBG  4      // batch groups (8 batches each)
#define NJG  32     // j groups (16 hidden units each)
#define GRP  32     // blocks per batch group

#define W_PAD   518
#define H_PAD   520
#define RED_PAD 33

__device__ float g_embed[Mn * En];
__device__ float g_a1[Mn * En];
__device__ float g_a[Mn * 3];
__device__ float g_attn[Mn * 3];
__device__ float g_xproj[(size_t)Mn * Gn];
__device__ float g_enc[(size_t)Mn * Hn];
__device__ float g_ctx[(size_t)Mn * Hn];
__device__ float g_pred[Mn];
__device__ float g_h[2 * Bn * Hn];
__device__ unsigned g_flag[NBG * GRP * 8];   // flag barrier: one 32B slot per block
__device__ unsigned g_pcnt[NBG * 32];

// ---- packed f32x2 helpers ----
__device__ __forceinline__ unsigned long long fma2(unsigned long long a,
                                                   unsigned long long b,
                                                   unsigned long long c) {
    unsigned long long d;
    asm("fma.rn.f32x2 %0, %1, %2, %3;" : "=l"(d) : "l"(a), "l"(b), "l"(c));
    return d;
}
__device__ __forceinline__ float2 unpack2(unsigned long long v) {
    float2 r; asm("mov.b64 {%0,%1}, %2;" : "=f"(r.x), "=f"(r.y) : "l"(v)); return r;
}
__device__ __forceinline__ unsigned long long pack2(float lo, float hi) {
    unsigned long long v; asm("mov.b64 %0, {%1,%2};" : "=l"(v) : "f"(lo), "f"(hi)); return v;
}

// ---- flag-array barrier: per-block release slot + 32-lane acquire poll ----
// No atomic fan-in: arrival is a single st.release to the block's own slot.
__device__ __forceinline__ void grp_bar(int bg, int rank, unsigned phase) {
    __syncthreads();
    unsigned target = phase + 1u;
    if (threadIdx.x == 0) {
        asm volatile("st.release.gpu.u32 [%0], %1;"
                     :: "l"(&g_flag[(bg * GRP + rank) * 8]), "r"(target) : "memory");
    }
    if (threadIdx.x < 32) {
        unsigned v;
        do {
            asm volatile("ld.acquire.gpu.u32 %0, [%1];"
                         : "=r"(v) : "l"(&g_flag[(bg * GRP + (int)threadIdx.x) * 8]) : "memory");
        } while (__any_sync(0xffffffffu, v < target));
    }
    __syncthreads();
}

// ---- fast activations (MUFU-based; inputs clamped, abs err ~1e-7) ----
__device__ __forceinline__ float fast_sigmoid(float x) {
    x = fminf(fmaxf(x, -20.f), 20.f);
    return __fdividef(1.0f, 1.0f + __expf(-x));
}
__device__ __forceinline__ float fast_tanh(float x) {
    x = fminf(fmaxf(x, -15.f), 15.f);
    float e = __expf(2.0f * x);
    return __fdividef(e - 1.0f, e + 1.0f);
}

// ---------------------------------------------------------------------------
// SIMT SGEMM, BK=16, register double-buffered, packed f32x2 FMA (unchanged)
// ---------------------------------------------------------------------------
__global__ void __launch_bounds__(256) sgemm_kernel(
    const float* __restrict__ A, const float* __restrict__ B, float* __restrict__ C,
    int M, int N, int K, int lda, int ldb, int koff,
    const float* __restrict__ bias1, const float* __restrict__ bias2, int relu)
{
    __shared__ float As[16][128];
    __shared__ float Bs[16][128];
    const int tid = threadIdx.x, bx = blockIdx.x, by = blockIdx.y;
    const int tx = tid & 15, ty = tid >> 4;
    const int arow = tid >> 1, acol = (tid & 1) * 8;
    const float* Ag = A + (size_t)(by * 128 + arow) * lda + acol;
    const float* Bg = B + (size_t)(bx * 128 + arow) * ldb + koff + acol;

    unsigned long long acc2[8][4];
    #pragma unroll
    for (int i = 0; i < 8; ++i)
        #pragma unroll
        for (int j = 0; j < 4; ++j) acc2[i][j] = 0ull;

    float4 pa0 = *(const float4*)(Ag);
    float4 pa1 = *(const float4*)(Ag + 4);
    float pb[8];
    #pragma unroll
    for (int i = 0; i < 8; ++i) pb[i] = Bg[i];

    for (int k0 = 0; k0 < K; k0 += 16) {
        As[acol + 0][arow] = pa0.x; As[acol + 1][arow] = pa0.y;
        As[acol + 2][arow] = pa0.z; As[acol + 3][arow] = pa0.w;
        As[acol + 4][arow] = pa1.x; As[acol + 5][arow] = pa1.y;
        As[acol + 6][arow] = pa1.z; As[acol + 7][arow] = pa1.w;
        #pragma unroll
        for (int i = 0; i < 8; ++i) Bs[acol + i][arow] = pb[i];
        __syncthreads();

        if (k0 + 16 < K) {
            pa0 = *(const float4*)(Ag + k0 + 16);
            pa1 = *(const float4*)(Ag + k0 + 20);
            #pragma unroll
            for (int i = 0; i < 8; ++i) pb[i] = Bg[k0 + 16 + i];
        }

        #pragma unroll
        for (int kk = 0; kk < 16; ++kk) {
            float4 ra0 = *(const float4*)&As[kk][ty * 8];
            float4 ra1 = *(const float4*)&As[kk][ty * 8 + 4];
            ulonglong2 rb0 = *(const ulonglong2*)&Bs[kk][tx * 8];
            ulonglong2 rb1 = *(const ulonglong2*)&Bs[kk][tx * 8 + 4];
            float ra[8] = {ra0.x, ra0.y, ra0.z, ra0.w, ra1.x, ra1.y, ra1.z, ra1.w};
            #pragma unroll
            for (int i = 0; i < 8; ++i) {
                unsigned long long ap = pack2(ra[i], ra[i]);
                acc2[i][0] = fma2(ap, rb0.x, acc2[i][0]);
                acc2[i][1] = fma2(ap, rb0.y, acc2[i][1]);
                acc2[i][2] = fma2(ap, rb1.x, acc2[i][2]);
                acc2[i][3] = fma2(ap, rb1.y, acc2[i][3]);
            }
        }
        __syncthreads();
    }
    #pragma unroll
    for (int i = 0; i < 8; ++i) {
        int m = by * 128 + ty * 8 + i;
        #pragma unroll
        for (int jp = 0; jp < 4; ++jp) {
            float2 v = unpack2(acc2[i][jp]);
            int n = bx * 128 + tx * 8 + jp * 2;
            float v0 = v.x, v1 = v.y;
            if (bias1) { v0 += bias1[n]; v1 += bias1[n + 1]; }
            if (bias2) { v0 += bias2[n]; v1 += bias2[n + 1]; }
            if (relu)  { v0 = fmaxf(v0, 0.f); v1 = fmaxf(v1, 0.f); }
            C[(size_t)m * N + n]     = v0;
            C[(size_t)m * N + n + 1] = v1;
        }
    }
}

__global__ void attn_logits_kernel(const float* __restrict__ a1,
                                   const float* __restrict__ W_a2,
                                   const float* __restrict__ b_a2,
                                   float* __restrict__ a)
{
    int gw = (blockIdx.x * blockDim.x + threadIdx.x) >> 5;
    int lane = threadIdx.x & 31;
    if (gw >= Mn) return;
    float4 v = ((const float4*)(a1 + (size_t)gw * En))[lane];
    #pragma unroll
    for (int l = 0; l < 3; ++l) {
        float4 wv = ((const float4*)(W_a2 + l * En))[lane];
        float s = v.x * wv.x + v.y * wv.y + v.z * wv.z + v.w * wv.w;
        #pragma unroll
        for (int o = 16; o; o >>= 1) s += __shfl_xor_sync(0xffffffffu, s, o);
        if (lane == 0) a[(size_t)gw * 3 + l] = s + b_a2[l];
    }
}

__global__ void softmax_time_kernel(const float* __restrict__ a, float* __restrict__ attn)
{
    __shared__ float red[256];
    int b = blockIdx.x / 3, l = blockIdx.x - b * 3;
    const float* base = a + (size_t)b * Sn * 3 + l;
    float mx = -3.4e38f;
    for (int s = threadIdx.x; s < Sn; s += 256) mx = fmaxf(mx, base[(size_t)s * 3]);
    red[threadIdx.x] = mx; __syncthreads();
    for (int o = 128; o; o >>= 1) {
        if (threadIdx.x < o) red[threadIdx.x] = fmaxf(red[threadIdx.x], red[threadIdx.x + o]);
        __syncthreads();
    }
    mx = red[0]; __syncthreads();
    float sum = 0.f;
    for (int s = threadIdx.x; s < Sn; s += 256) sum += expf(base[(size_t)s * 3] - mx);
    red[threadIdx.x] = sum; __syncthreads();
    for (int o = 128; o; o >>= 1) {
        if (threadIdx.x < o) red[threadIdx.x] += red[threadIdx.x + o];
        __syncthreads();
    }
    float inv = 1.f / red[0];
    float* ob = attn + (size_t)b * Sn * 3 + l;
    for (int s = threadIdx.x; s < Sn; s += 256)
        ob[(size_t)s * 3] = expf(base[(size_t)s * 3] - mx) * inv;
}

__global__ void context_kernel(const float* __restrict__ attn,
                               const float* __restrict__ enc,
                               float* __restrict__ ctx)
{
    int m = blockIdx.x;
    int t = m & (Sn - 1);
    float a0 = attn[(size_t)m * 3 + 0];
    float a1 = attn[(size_t)m * 3 + 1];
    float a2 = attn[(size_t)m * 3 + 2];
    float4 e0 = ((const float4*)(enc + (size_t)m * Hn))[threadIdx.x];
    float4 r; r.x = a0 * e0.x; r.y = a0 * e0.y; r.z = a0 * e0.z; r.w = a0 * e0.w;
    if (t >= 1) {
        float4 e1 = ((const float4*)(enc + (size_t)(m - 1) * Hn))[threadIdx.x];
        r.x += a1 * e1.x; r.y += a1 * e1.y; r.z += a1 * e1.z; r.w += a1 * e1.w;
    }
    if (t >= 2) {
        float4 e2 = ((const float4*)(enc + (size_t)(m - 2) * Hn))[threadIdx.x];
        r.x += a2 * e2.x; r.y += a2 * e2.y; r.z += a2 * e2.z; r.w += a2 * e2.w;
    }
    ((float4*)(ctx + (size_t)m * Hn))[threadIdx.x] = r;
}

__global__ void init_enc_kernel(const float* __restrict__ h0)
{
    int i = blockIdx.x * 256 + threadIdx.x;
    if (i < Bn * Hn) g_h[i] = h0[i & (Hn - 1)];
    if (i < NBG * GRP * 8) g_flag[i] = 0u;
    if (i < NBG * 32) g_pcnt[i] = 0u;
}

__global__ void init_dec_kernel(const float* __restrict__ h0, const float* __restrict__ b_o2)
{
    int i = blockIdx.x * 256 + threadIdx.x;
    if (i < Bn * Hn) g_h[i] = h0[i & (Hn - 1)];
    if (i < Mn) g_pred[i] = b_o2[0];
    if (i < NBG * GRP * 8) g_flag[i] = 0u;
    if (i < NBG * 32) g_pcnt[i] = 0u;
}

// ===========================================================================
// Encoder LSTM: 128 blocks = 4 bg x 32 jg. Register-tiled recurrent matmul.
// ===========================================================================
#define ENC_SMEM ((64 * W_PAD + 8 * H_PAD + 256 * RED_PAD) * 4)
__global__ void __launch_bounds__(256, 1) lstm_enc_kernel(
    const float* __restrict__ xproj, const float* __restrict__ Whh,
    const float* __restrict__ c0, const int* __restrict__ lengths,
    float* __restrict__ enc_out)
{
    extern __shared__ float sm[];
    float* w_s   = sm;                         // [64][W_PAD]
    float* h_s   = sm + 64 * W_PAD;            // [8][H_PAD]
    float* red_s = h_s + 8 * H_PAD;            // [256][RED_PAD]

    const int bg = blockIdx.x & 3, jg = blockIdx.x >> 2;
    const int tid = threadIdx.x;
    const int mj = tid & 15, mkc = tid >> 4;
    const int cb = tid >> 4, cj = tid & 15;
    const bool is_cons = (tid < 128);
    const int b = bg * 8 + cb;
    const int j = jg * 16 + cj;

    for (int i = tid; i < 64 * 512; i += 256) {
        int lr = i >> 9, k = i & 511;
        w_s[lr * W_PAD + k] = Whh[(size_t)((lr >> 4) * Hn + jg * 16 + (lr & 15)) * Hn + k];
    }
    float c_reg = is_cons ? c0[j] : 0.f;
    const int len_b = is_cons ? lengths[b] : 0;
    __syncthreads();

    const float* w0p = w_s + (0 * 16 + mj) * W_PAD + mkc * 32;
    const float* w1p = w_s + (1 * 16 + mj) * W_PAD + mkc * 32;
    const float* w2p = w_s + (2 * 16 + mj) * W_PAD + mkc * 32;
    const float* w3p = w_s + (3 * 16 + mj) * W_PAD + mkc * 32;
    const float* hb  = h_s + mkc * 32;

    for (int t = 0; t < Sn; ++t) {
        const float4* src = (const float4*)(g_h + (t & 1) * (Bn * Hn) + bg * 8 * Hn);
        #pragma unroll
        for (int i = 0; i < 4; ++i) {
            int idx = tid + i * 256;
            float4 v = __ldcg(src + idx);
            ((float4*)(h_s + (idx >> 7) * H_PAD))[idx & 127] = v;
        }
        float xp0 = 0.f, xp1 = 0.f, xp2 = 0.f, xp3 = 0.f;
        if (is_cons) {
            const float* xp = xproj + ((size_t)b * Sn + t) * Gn + j;
            xp0 = xp[0]; xp1 = xp[512]; xp2 = xp[1024]; xp3 = xp[1536];
        }
        __syncthreads();

        unsigned long long acc[4][8];
        #pragma unroll
        for (int g = 0; g < 4; ++g)
            #pragma unroll
            for (int bb = 0; bb < 8; ++bb) acc[g][bb] = 0ull;

        #pragma unroll 4
        for (int it = 0; it < 16; ++it) {
            unsigned long long wv0 = *(const unsigned long long*)(w0p + it * 2);
            unsigned long long wv1 = *(const unsigned long long*)(w1p + it * 2);
            unsigned long long wv2 = *(const unsigned long long*)(w2p + it * 2);
            unsigned long long wv3 = *(const unsigned long long*)(w3p + it * 2);
            unsigned long long hv[8];
            #pragma unroll
            for (int bb = 0; bb < 8; ++bb)
                hv[bb] = *(const unsigned long long*)(hb + bb * H_PAD + it * 2);
            #pragma unroll
            for (int bb = 0; bb < 8; ++bb) {
                acc[0][bb] = fma2(wv0, hv[bb], acc[0][bb]);
                acc[1][bb] = fma2(wv1, hv[bb], acc[1][bb]);
                acc[2][bb] = fma2(wv2, hv[bb], acc[2][bb]);
                acc[3][bb] = fma2(wv3, hv[bb], acc[3][bb]);
            }
        }
        float* r = red_s + tid * RED_PAD;
        #pragma unroll
        for (int g = 0; g < 4; ++g)
            #pragma unroll
            for (int bb = 0; bb < 8; ++bb) {
                float2 u = unpack2(acc[g][bb]);
                r[g * 8 + bb] = u.x + u.y;
            }
        __syncthreads();

        if (is_cons) {
            float gi = xp0, gf = xp1, gg = xp2, go = xp3;
            #pragma unroll
            for (int kc = 0; kc < 16; ++kc) {
                const float* rr = red_s + (kc * 16 + cj) * RED_PAD + cb;
                gi += rr[0]; gf += rr[8]; gg += rr[16]; go += rr[24];
            }
            float si = fast_sigmoid(gi), sf = fast_sigmoid(gf), so = fast_sigmoid(go);
            c_reg = sf * c_reg + si * fast_tanh(gg);
            float hh = so * fast_tanh(c_reg);
            __stcg(&g_h[((t + 1) & 1) * (Bn * Hn) + b * Hn + j], hh);
            enc_out[((size_t)b * Sn + t) * Hn + j] = (t < len_b) ? hh : 0.f;
        }
        grp_bar(bg, jg, (unsigned)t);
    }
}

// ===========================================================================
// Decoder LSTM: one flag barrier per step + early p-arrival counter (red.add).
// ===========================================================================
#define DEC_SMEM ((64 * W_PAD + 8 * H_PAD + 256 * RED_PAD + 4 * 516 + 64) * 4)
__global__ void __launch_bounds__(256, 1) lstm_dec_kernel(
    const float* __restrict__ ctxproj, const float* __restrict__ Whh,
    const float* __restrict__ Wih, const float* __restrict__ c0,
    const float* __restrict__ W_o1, const float* __restrict__ b_o1,
    const float* __restrict__ W_o2)
{
    extern __shared__ float sm[];
    float* w_s   = sm;                         // [64][W_PAD]
    float* h_s   = sm + 64 * W_PAD;            // [8][H_PAD]
    float* red_s = h_s + 8 * H_PAD;            // [256][RED_PAD]
    float* wo1_s = red_s + 256 * RED_PAD;      // [4][516]
    float* wp_s  = wo1_s + 4 * 516;            // [64]

    const int bg = blockIdx.x & 3, jg = blockIdx.x >> 2;
    const int tid = threadIdx.x;
    const int mj = tid & 15, mkc = tid >> 4;
    const int cb = tid >> 4, cj = tid & 15;
    const bool is_cons = (tid < 128);
    const int b = bg * 8 + cb;
    const int j = jg * 16 + cj;
    const int warp = tid >> 5, lane = tid & 31;

    for (int i = tid; i < 64 * 512; i += 256) {
        int lr = i >> 9, k = i & 511;
        w_s[lr * W_PAD + k] = Whh[(size_t)((lr >> 4) * Hn + jg * 16 + (lr & 15)) * Hn + k];
    }
    for (int i = tid; i < 4 * 512; i += 256) {
        int e = i >> 9, k = i & 511;
        wo1_s[e * 516 + k] = W_o1[(size_t)(jg * 4 + e) * Hn + k];
    }
    if (tid < 64) {
        wp_s[tid] = Wih[(size_t)((tid >> 4) * Hn + jg * 16 + (tid & 15)) * 513];
    }
    float wo2_r[4], bo1_r[4];
    #pragma unroll
    for (int e = 0; e < 4; ++e) { wo2_r[e] = W_o2[jg * 4 + e]; bo1_r[e] = b_o1[jg * 4 + e]; }
    float c_reg = is_cons ? c0[j] : 0.f;
    __syncthreads();

    const float* w0p = w_s + (0 * 16 + mj) * W_PAD + mkc * 32;
    const float* w1p = w_s + (1 * 16 + mj) * W_PAD + mkc * 32;
    const float* w2p = w_s + (2 * 16 + mj) * W_PAD + mkc * 32;
    const float* w3p = w_s + (3 * 16 + mj) * W_PAD + mkc * 32;
    const float* hb  = h_s + mkc * 32;

    for (int t = 0; t < Sn; ++t) {
        const float4* src = (const float4*)(g_h + (t & 1) * (Bn * Hn) + bg * 8 * Hn);
        #pragma unroll
        for (int i = 0; i < 4; ++i) {
            int idx = tid + i * 256;
            float4 v = __ldcg(src + idx);
            ((float4*)(h_s + (idx >> 7) * H_PAD))[idx & 127] = v;
        }
        float xp0 = 0.f, xp1 = 0.f, xp2 = 0.f, xp3 = 0.f;
        if (is_cons) {
            const float* xp = ctxproj + ((size_t)b * Sn + t) * Gn + j;
            xp0 = xp[0]; xp1 = xp[512]; xp2 = xp[1024]; xp3 = xp[1536];
        }
        __syncthreads();

        // output-MLP partials for p[t-1]; post arrival early (fire-and-forget)
        if (t > 0) {
            float padd = 0.f;
            #pragma unroll
            for (int e = 0; e < 4; ++e) {
                float s = 0.f;
                #pragma unroll
                for (int kk = 0; kk < 16; ++kk) {
                    int k = kk * 32 + lane;
                    s += wo1_s[e * 516 + k] * h_s[warp * H_PAD + k];
                }
                #pragma unroll
                for (int o = 16; o; o >>= 1) s += __shfl_xor_sync(0xffffffffu, s, o);
                padd += fmaxf(s + bo1_r[e], 0.f) * wo2_r[e];
            }
            if (lane == 0)
                atomicAdd(&g_pred[(bg * 8 + warp) * Sn + (t - 1)], padd);
            __syncthreads();
            if (tid == 0) {
                asm volatile("red.release.gpu.global.add.u32 [%0], %1;"
                             :: "l"(&g_pcnt[bg * 32]), "r"(1u) : "memory");
            }
        }

        unsigned long long acc[4][8];
        #pragma unroll
        for (int g = 0; g < 4; ++g)
            #pragma unroll
            for (int bb = 0; bb < 8; ++bb) acc[g][bb] = 0ull;

        #pragma unroll 4
        for (int it = 0; it < 16; ++it) {
            unsigned long long wv0 = *(const unsigned long long*)(w0p + it * 2);
            unsigned long long wv1 = *(const unsigned long long*)(w1p + it * 2);
            unsigned long long wv2 = *(const unsigned long long*)(w2p + it * 2);
            unsigned long long wv3 = *(const unsigned long long*)(w3p + it * 2);
            unsigned long long hv[8];
            #pragma unroll
            for (int bb = 0; bb < 8; ++bb)
                hv[bb] = *(const unsigned long long*)(hb + bb * H_PAD + it * 2);
            #pragma unroll
            for (int bb = 0; bb < 8; ++bb) {
                acc[0][bb] = fma2(wv0, hv[bb], acc[0][bb]);
                acc[1][bb] = fma2(wv1, hv[bb], acc[1][bb]);
                acc[2][bb] = fma2(wv2, hv[bb], acc[2][bb]);
                acc[3][bb] = fma2(wv3, hv[bb], acc[3][bb]);
            }
        }
        float* r = red_s + tid * RED_PAD;
        #pragma unroll
        for (int g = 0; g < 4; ++g)
            #pragma unroll
            for (int bb = 0; bb < 8; ++bb) {
                float2 u = unpack2(acc[g][bb]);
                r[g * 8 + bb] = u.x + u.y;
            }

        // wait for all blocks' p[t-1] posts (usually already satisfied)
        if (tid == 0 && t > 0) {
            unsigned rr;
            do {
                asm volatile("ld.acquire.gpu.u32 %0, [%1];"
                             : "=r"(rr) : "l"(&g_pcnt[bg * 32]) : "memory");
            } while (rr < 32u * (unsigned)t);
        }
        __syncthreads();

        if (is_cons) {
            float p_prev = (t > 0) ? __ldcg(&g_pred[b * Sn + (t - 1)]) : 0.f;
            float gi = xp0 + p_prev * wp_s[0 * 16 + cj];
            float gf = xp1 + p_prev * wp_s[1 * 16 + cj];
            float gg = xp2 + p_prev * wp_s[2 * 16 + cj];
            float go = xp3 + p_prev * wp_s[3 * 16 + cj];
            #pragma unroll
            for (int kc = 0; kc < 16; ++kc) {
                const float* rr = red_s + (kc * 16 + cj) * RED_PAD + cb;
                gi += rr[0]; gf += rr[8]; gg += rr[16]; go += rr[24];
            }
            float si = fast_sigmoid(gi), sf = fast_sigmoid(gf), so = fast_sigmoid(go);
            c_reg = sf * c_reg + si * fast_tanh(gg);
            float hh = so * fast_tanh(c_reg);
            __stcg(&g_h[((t + 1) & 1) * (Bn * Hn) + b * Hn + j], hh);
        }
        grp_bar(bg, jg, (unsigned)t);
    }

    // final step's output MLP (t = Sn-1)
    {
        const float4* src = (const float4*)(g_h + (Sn & 1) * (Bn * Hn) + bg * 8 * Hn);
        #pragma unroll
        for (int i = 0; i < 4; ++i) {
            int idx = tid + i * 256;
            float4 v = __ldcg(src + idx);
            ((float4*)(h_s + (idx >> 7) * H_PAD))[idx & 127] = v;
        }
        __syncthreads();
        float padd = 0.f;
        #pragma unroll
        for (int e = 0; e < 4; ++e) {
            float s = 0.f;
            #pragma unroll
            for (int kk = 0; kk < 16; ++kk) {
                int k = kk * 32 + lane;
                s += wo1_s[e * 516 + k] * h_s[warp * H_PAD + k];
            }
            #pragma unroll
            for (int o = 16; o; o >>= 1) s += __shfl_xor_sync(0xffffffffu, s, o);
            padd += fmaxf(s + bo1_r[e], 0.f) * wo2_r[e];
        }
        if (lane == 0)
            atomicAdd(&g_pred[(bg * 8 + warp) * Sn + (Sn - 1)], padd);
    }
}

__global__ void finalize_kernel(const float* __restrict__ mask, float* __restrict__ out)
{
    int i = blockIdx.x * 256 + threadIdx.x;
    if (i < Mn) out[i] = g_pred[i] * mask[i];
}

extern "C" void kernel_launch(void* const* d_in, const int* in_sizes, int n_in,
                              void* d_out, int out_size)
{
    const float* inputs  = (const float*)d_in[0];
    const float* mask    = (const float*)d_in[1];
    const int*   lengths = (const int*)  d_in[2];
    const float* W_e     = (const float*)d_in[3];
    const float* b_e     = (const float*)d_in[4];
    const float* W_a1    = (const float*)d_in[5];
    const float* b_a1    = (const float*)d_in[6];
    const float* W_a2    = (const float*)d_in[7];
    const float* b_a2    = (const float*)d_in[8];
    const float* Wih_e   = (const float*)d_in[9];
    const float* Whh_e   = (const float*)d_in[10];
    const float* bih_e   = (const float*)d_in[11];
    const float* bhh_e   = (const float*)d_in[12];
    const float* enc_h0  = (const float*)d_in[13];
    const float* enc_c0  = (const float*)d_in[14];
    const float* Wih_d   = (const float*)d_in[15];
    const float* Whh_d   = (const float*)d_in[16];
    const float* bih_d   = (const float*)d_in[17];
    const float* bhh_d   = (const float*)d_in[18];
    const float* dec_h0  = (const float*)d_in[19];
    const float* dec_c0  = (const float*)d_in[20];
    const float* W_o1    = (const float*)d_in[21];
    const float* b_o1    = (const float*)d_in[22];
    const float* W_o2    = (const float*)d_in[23];
    const float* b_o2    = (const float*)d_in[24];
    float* out = (float*)d_out;

    float *p_embed, *p_a1, *p_a, *p_attn, *p_xproj, *p_enc, *p_ctx;
    cudaGetSymbolAddress((void**)&p_embed, g_embed);
    cudaGetSymbolAddress((void**)&p_a1,    g_a1);
    cudaGetSymbolAddress((void**)&p_a,     g_a);
    cudaGetSymbolAddress((void**)&p_attn,  g_attn);
    cudaGetSymbolAddress((void**)&p_xproj, g_xproj);
    cudaGetSymbolAddress((void**)&p_enc,   g_enc);
    cudaGetSymbolAddress((void**)&p_ctx,   g_ctx);

    cudaFuncSetAttribute(lstm_enc_kernel, cudaFuncAttributeMaxDynamicSharedMemorySize, ENC_SMEM);
    cudaFuncSetAttribute(lstm_dec_kernel, cudaFuncAttributeMaxDynamicSharedMemorySize, DEC_SMEM);

    sgemm_kernel<<<dim3(En / 128, Mn / 128), 256>>>(
        inputs, W_e, p_embed, Mn, En, 1024, 1024, 1024, 0, b_e, nullptr, 1);
    sgemm_kernel<<<dim3(En / 128, Mn / 128), 256>>>(
        p_embed, W_a1, p_a1, Mn, En, En, En, En, 0, b_a1, nullptr, 1);
    attn_logits_kernel<<<Mn / 8, 256>>>(p_a1, W_a2, b_a2, p_a);
    softmax_time_kernel<<<Bn * 3, 256>>>(p_a, p_attn);
    sgemm_kernel<<<dim3(Gn / 128, Mn / 128), 256>>>(
        p_embed, Wih_e, p_xproj, Mn, Gn, En, En, En, 0, bih_e, bhh_e, 0);
    init_enc_kernel<<<(Bn * Hn + 255) / 256, 256>>>(enc_h0);
    lstm_enc_kernel<<<NBG * NJG, 256, ENC_SMEM>>>(p_xproj, Whh_e, enc_c0, lengths, p_enc);
    context_kernel<<<Mn, Hn / 4>>>(p_attn, p_enc, p_ctx);
    sgemm_kernel<<<dim3(Gn / 128, Mn / 128), 256>>>(
        p_ctx, Wih_d, p_xproj, Mn, Gn, Hn, Hn, Hn + 1, 1, bih_d, bhh_d, 0);
    init_dec_kernel<<<(Mn + 255) / 256, 256>>>(dec_h0, b_o2);
    lstm_dec_kernel<<<NBG * NJG, 256, DEC_SMEM>>>(p_xproj, Whh_d, Wih_d, dec_c0, W_o1, b_o1, W_o2);
    finalize_kernel<<<(Mn + 255) / 256, 256>>>(mask, out);
}

// round 13
// speedup vs baseline: 1.0821x; 1.0821x over previous
#include <cuda_runtime.h>
#include <math.h>

#define Bn   32
#define Sn   1024
#define En   128
#define Hn   512
#define Gn   2048
#define Mn   32768
#define NBG  4      // batch groups (8 batches each)
#define NJG  32     // j groups (16 hidden units each)
#define GRP  32     // blocks per batch group

#define W_PAD   518
#define H_PAD   520
#define RED_PAD 41   // gather-friendly: tid*41 mod 32 = tid*9 (9 invertible mod 32)

__device__ float g_embed[Mn * En];
__device__ float g_a1[Mn * En];
__device__ float g_a[Mn * 3];
__device__ float g_attn[Mn * 3];
__device__ float g_xproj[(size_t)Mn * Gn];
__device__ float g_enc[(size_t)Mn * Hn];
__device__ float g_ctx[(size_t)Mn * Hn];
__device__ float g_pred[Mn];
__device__ float g_h[2 * Bn * Hn];
__device__ unsigned g_cnt[NBG * 32];
__device__ unsigned g_rel[NBG * 32];
__device__ unsigned g_pcnt[NBG * 32];

// ---- packed f32x2 helpers ----
__device__ __forceinline__ unsigned long long fma2(unsigned long long a,
                                                   unsigned long long b,
                                                   unsigned long long c) {
    unsigned long long d;
    asm("fma.rn.f32x2 %0, %1, %2, %3;" : "=l"(d) : "l"(a), "l"(b), "l"(c));
    return d;
}
__device__ __forceinline__ float2 unpack2(unsigned long long v) {
    float2 r; asm("mov.b64 {%0,%1}, %2;" : "=f"(r.x), "=f"(r.y) : "l"(v)); return r;
}
__device__ __forceinline__ unsigned long long pack2(float lo, float hi) {
    unsigned long long v; asm("mov.b64 %0, {%1,%2};" : "=l"(v) : "f"(lo), "f"(hi)); return v;
}

// ---- per-group acquire/release barrier (GRP arrivals; single atomic line) ----
__device__ __forceinline__ void grp_bar(int g, unsigned phase) {
    __syncthreads();
    if (threadIdx.x == 0) {
        unsigned v;
        asm volatile("atom.acq_rel.gpu.add.u32 %0, [%1], %2;"
                     : "=r"(v) : "l"(&g_cnt[g * 32]), "r"(1u) : "memory");
        if (v == phase * (unsigned)GRP + (unsigned)(GRP - 1)) {
            asm volatile("st.release.gpu.u32 [%0], %1;"
                         :: "l"(&g_rel[g * 32]), "r"(phase + 1u) : "memory");
        } else {
            unsigned r;
            do {
                asm volatile("ld.acquire.gpu.u32 %0, [%1];"
                             : "=r"(r) : "l"(&g_rel[g * 32]) : "memory");
            } while (r < phase + 1u);
        }
    }
    __syncthreads();
}

// ---- fast activations (MUFU-based; inputs clamped) ----
__device__ __forceinline__ float fast_sigmoid(float x) {
    x = fminf(fmaxf(x, -20.f), 20.f);
    return __fdividef(1.0f, 1.0f + __expf(-x));
}
__device__ __forceinline__ float fast_tanh(float x) {
    x = fminf(fmaxf(x, -15.f), 15.f);
    float e = __expf(2.0f * x);
    return __fdividef(e - 1.0f, e + 1.0f);
}

__device__ __forceinline__ float sigmoidf_(float x) { return 1.0f / (1.0f + expf(-x)); }

// ---------------------------------------------------------------------------
// SIMT SGEMM, BK=16, register double-buffered, packed f32x2 FMA
// ---------------------------------------------------------------------------
__global__ void __launch_bounds__(256) sgemm_kernel(
    const float* __restrict__ A, const float* __restrict__ B, float* __restrict__ C,
    int M, int N, int K, int lda, int ldb, int koff,
    const float* __restrict__ bias1, const float* __restrict__ bias2, int relu)
{
    __shared__ float As[16][128];
    __shared__ float Bs[16][128];
    const int tid = threadIdx.x, bx = blockIdx.x, by = blockIdx.y;
    const int tx = tid & 15, ty = tid >> 4;
    const int arow = tid >> 1, acol = (tid & 1) * 8;
    const float* Ag = A + (size_t)(by * 128 + arow) * lda + acol;
    const float* Bg = B + (size_t)(bx * 128 + arow) * ldb + koff + acol;

    unsigned long long acc2[8][4];
    #pragma unroll
    for (int i = 0; i < 8; ++i)
        #pragma unroll
        for (int j = 0; j < 4; ++j) acc2[i][j] = 0ull;

    float4 pa0 = *(const float4*)(Ag);
    float4 pa1 = *(const float4*)(Ag + 4);
    float pb[8];
    #pragma unroll
    for (int i = 0; i < 8; ++i) pb[i] = Bg[i];

    for (int k0 = 0; k0 < K; k0 += 16) {
        As[acol + 0][arow] = pa0.x; As[acol + 1][arow] = pa0.y;
        As[acol + 2][arow] = pa0.z; As[acol + 3][arow] = pa0.w;
        As[acol + 4][arow] = pa1.x; As[acol + 5][arow] = pa1.y;
        As[acol + 6][arow] = pa1.z; As[acol + 7][arow] = pa1.w;
        #pragma unroll
        for (int i = 0; i < 8; ++i) Bs[acol + i][arow] = pb[i];
        __syncthreads();

        if (k0 + 16 < K) {
            pa0 = *(const float4*)(Ag + k0 + 16);
            pa1 = *(const float4*)(Ag + k0 + 20);
            #pragma unroll
            for (int i = 0; i < 8; ++i) pb[i] = Bg[k0 + 16 + i];
        }

        #pragma unroll
        for (int kk = 0; kk < 16; ++kk) {
            float4 ra0 = *(const float4*)&As[kk][ty * 8];
            float4 ra1 = *(const float4*)&As[kk][ty * 8 + 4];
            ulonglong2 rb0 = *(const ulonglong2*)&Bs[kk][tx * 8];
            ulonglong2 rb1 = *(const ulonglong2*)&Bs[kk][tx * 8 + 4];
            float ra[8] = {ra0.x, ra0.y, ra0.z, ra0.w, ra1.x, ra1.y, ra1.z, ra1.w};
            #pragma unroll
            for (int i = 0; i < 8; ++i) {
                unsigned long long ap = pack2(ra[i], ra[i]);
                acc2[i][0] = fma2(ap, rb0.x, acc2[i][0]);
                acc2[i][1] = fma2(ap, rb0.y, acc2[i][1]);
                acc2[i][2] = fma2(ap, rb1.x, acc2[i][2]);
                acc2[i][3] = fma2(ap, rb1.y, acc2[i][3]);
            }
        }
        __syncthreads();
    }
    #pragma unroll
    for (int i = 0; i < 8; ++i) {
        int m = by * 128 + ty * 8 + i;
        #pragma unroll
        for (int jp = 0; jp < 4; ++jp) {
            float2 v = unpack2(acc2[i][jp]);
            int n = bx * 128 + tx * 8 + jp * 2;
            float v0 = v.x, v1 = v.y;
            if (bias1) { v0 += bias1[n]; v1 += bias1[n + 1]; }
            if (bias2) { v0 += bias2[n]; v1 += bias2[n + 1]; }
            if (relu)  { v0 = fmaxf(v0, 0.f); v1 = fmaxf(v1, 0.f); }
            C[(size_t)m * N + n]     = v0;
            C[(size_t)m * N + n + 1] = v1;
        }
    }
}

__global__ void attn_logits_kernel(const float* __restrict__ a1,
                                   const float* __restrict__ W_a2,
                                   const float* __restrict__ b_a2,
                                   float* __restrict__ a)
{
    int gw = (blockIdx.x * blockDim.x + threadIdx.x) >> 5;
    int lane = threadIdx.x & 31;
    if (gw >= Mn) return;
    float4 v = ((const float4*)(a1 + (size_t)gw * En))[lane];
    #pragma unroll
    for (int l = 0; l < 3; ++l) {
        float4 wv = ((const float4*)(W_a2 + l * En))[lane];
        float s = v.x * wv.x + v.y * wv.y + v.z * wv.z + v.w * wv.w;
        #pragma unroll
        for (int o = 16; o; o >>= 1) s += __shfl_xor_sync(0xffffffffu, s, o);
        if (lane == 0) a[(size_t)gw * 3 + l] = s + b_a2[l];
    }
}

__global__ void softmax_time_kernel(const float* __restrict__ a, float* __restrict__ attn)
{
    __shared__ float red[256];
    int b = blockIdx.x / 3, l = blockIdx.x - b * 3;
    const float* base = a + (size_t)b * Sn * 3 + l;
    float mx = -3.4e38f;
    for (int s = threadIdx.x; s < Sn; s += 256) mx = fmaxf(mx, base[(size_t)s * 3]);
    red[threadIdx.x] = mx; __syncthreads();
    for (int o = 128; o; o >>= 1) {
        if (threadIdx.x < o) red[threadIdx.x] = fmaxf(red[threadIdx.x], red[threadIdx.x + o]);
        __syncthreads();
    }
    mx = red[0]; __syncthreads();
    float sum = 0.f;
    for (int s = threadIdx.x; s < Sn; s += 256) sum += expf(base[(size_t)s * 3] - mx);
    red[threadIdx.x] = sum; __syncthreads();
    for (int o = 128; o; o >>= 1) {
        if (threadIdx.x < o) red[threadIdx.x] += red[threadIdx.x + o];
        __syncthreads();
    }
    float inv = 1.f / red[0];
    float* ob = attn + (size_t)b * Sn * 3 + l;
    for (int s = threadIdx.x; s < Sn; s += 256)
        ob[(size_t)s * 3] = expf(base[(size_t)s * 3] - mx) * inv;
}

__global__ void context_kernel(const float* __restrict__ attn,
                               const float* __restrict__ enc,
                               float* __restrict__ ctx)
{
    int m = blockIdx.x;
    int t = m & (Sn - 1);
    float a0 = attn[(size_t)m * 3 + 0];
    float a1 = attn[(size_t)m * 3 + 1];
    float a2 = attn[(size_t)m * 3 + 2];
    float4 e0 = ((const float4*)(enc + (size_t)m * Hn))[threadIdx.x];
    float4 r; r.x = a0 * e0.x; r.y = a0 * e0.y; r.z = a0 * e0.z; r.w = a0 * e0.w;
    if (t >= 1) {
        float4 e1 = ((const float4*)(enc + (size_t)(m - 1) * Hn))[threadIdx.x];
        r.x += a1 * e1.x; r.y += a1 * e1.y; r.z += a1 * e1.z; r.w += a1 * e1.w;
    }
    if (t >= 2) {
        float4 e2 = ((const float4*)(enc + (size_t)(m - 2) * Hn))[threadIdx.x];
        r.x += a2 * e2.x; r.y += a2 * e2.y; r.z += a2 * e2.z; r.w += a2 * e2.w;
    }
    ((float4*)(ctx + (size_t)m * Hn))[threadIdx.x] = r;
}

__global__ void init_enc_kernel(const float* __restrict__ h0)
{
    int i = blockIdx.x * 256 + threadIdx.x;
    if (i < Bn * Hn) g_h[i] = h0[i & (Hn - 1)];
    if (i < NBG * 32) { g_cnt[i] = 0u; g_rel[i] = 0u; g_pcnt[i] = 0u; }
}

__global__ void init_dec_kernel(const float* __restrict__ h0, const float* __restrict__ b_o2)
{
    int i = blockIdx.x * 256 + threadIdx.x;
    if (i < Bn * Hn) g_h[i] = h0[i & (Hn - 1)];
    if (i < Mn) g_pred[i] = b_o2[0];
    if (i < NBG * 32) { g_cnt[i] = 0u; g_rel[i] = 0u; g_pcnt[i] = 0u; }
}

// ===========================================================================
// Encoder LSTM: 128 blocks = 4 bg x 32 jg. Register-tiled recurrent matmul.
// ===========================================================================
#define ENC_SMEM ((64 * W_PAD + 8 * H_PAD + 256 * RED_PAD) * 4)
__global__ void __launch_bounds__(256, 1) lstm_enc_kernel(
    const float* __restrict__ xproj, const float* __restrict__ Whh,
    const float* __restrict__ c0, const int* __restrict__ lengths,
    float* __restrict__ enc_out)
{
    extern __shared__ float sm[];
    float* w_s   = sm;                         // [64][W_PAD]
    float* h_s   = sm + 64 * W_PAD;            // [8][H_PAD]
    float* red_s = h_s + 8 * H_PAD;            // [256][RED_PAD]

    const int bg = blockIdx.x & 3, jg = blockIdx.x >> 2;
    const int tid = threadIdx.x;
    const int mj = tid & 15, mkc = tid >> 4;
    const int cb = tid >> 4, cj = tid & 15;
    const bool is_cons = (tid < 128);
    const int b = bg * 8 + cb;
    const int j = jg * 16 + cj;

    for (int i = tid; i < 64 * 512; i += 256) {
        int lr = i >> 9, k = i & 511;
        w_s[lr * W_PAD + k] = Whh[(size_t)((lr >> 4) * Hn + jg * 16 + (lr & 15)) * Hn + k];
    }
    float c_reg = is_cons ? c0[j] : 0.f;
    const int len_b = is_cons ? lengths[b] : 0;
    __syncthreads();

    const float* w0p = w_s + (0 * 16 + mj) * W_PAD + mkc * 32;
    const float* w1p = w_s + (1 * 16 + mj) * W_PAD + mkc * 32;
    const float* w2p = w_s + (2 * 16 + mj) * W_PAD + mkc * 32;
    const float* w3p = w_s + (3 * 16 + mj) * W_PAD + mkc * 32;
    const float* hb  = h_s + mkc * 32;

    for (int t = 0; t < Sn; ++t) {
        const float4* src = (const float4*)(g_h + (t & 1) * (Bn * Hn) + bg * 8 * Hn);
        #pragma unroll
        for (int i = 0; i < 4; ++i) {
            int idx = tid + i * 256;
            float4 v = __ldcg(src + idx);
            ((float4*)(h_s + (idx >> 7) * H_PAD))[idx & 127] = v;
        }
        float xp0 = 0.f, xp1 = 0.f, xp2 = 0.f, xp3 = 0.f;
        if (is_cons) {
            const float* xp = xproj + ((size_t)b * Sn + t) * Gn + j;
            xp0 = xp[0]; xp1 = xp[512]; xp2 = xp[1024]; xp3 = xp[1536];
        }
        __syncthreads();

        unsigned long long acc[4][8];
        #pragma unroll
        for (int g = 0; g < 4; ++g)
            #pragma unroll
            for (int bb = 0; bb < 8; ++bb) acc[g][bb] = 0ull;

        #pragma unroll 4
        for (int it = 0; it < 16; ++it) {
            unsigned long long wv0 = *(const unsigned long long*)(w0p + it * 2);
            unsigned long long wv1 = *(const unsigned long long*)(w1p + it * 2);
            unsigned long long wv2 = *(const unsigned long long*)(w2p + it * 2);
            unsigned long long wv3 = *(const unsigned long long*)(w3p + it * 2);
            unsigned long long hv[8];
            #pragma unroll
            for (int bb = 0; bb < 8; ++bb)
                hv[bb] = *(const unsigned long long*)(hb + bb * H_PAD + it * 2);
            #pragma unroll
            for (int bb = 0; bb < 8; ++bb) {
                acc[0][bb] = fma2(wv0, hv[bb], acc[0][bb]);
                acc[1][bb] = fma2(wv1, hv[bb], acc[1][bb]);
                acc[2][bb] = fma2(wv2, hv[bb], acc[2][bb]);
                acc[3][bb] = fma2(wv3, hv[bb], acc[3][bb]);
            }
        }
        float* r = red_s + tid * RED_PAD;
        #pragma unroll
        for (int g = 0; g < 4; ++g)
            #pragma unroll
            for (int bb = 0; bb < 8; ++bb) {
                float2 u = unpack2(acc[g][bb]);
                r[g * 8 + bb] = u.x + u.y;
            }
        __syncthreads();

        if (is_cons) {
            float gi = xp0, gf = xp1, gg = xp2, go = xp3;
            #pragma unroll
            for (int kc = 0; kc < 16; ++kc) {
                const float* rr = red_s + (kc * 16 + cj) * RED_PAD + cb;
                gi += rr[0]; gf += rr[8]; gg += rr[16]; go += rr[24];
            }
            float si = fast_sigmoid(gi), sf = fast_sigmoid(gf), so = fast_sigmoid(go);
            c_reg = sf * c_reg + si * fast_tanh(gg);
            float hh = so * fast_tanh(c_reg);
            __stcg(&g_h[((t + 1) & 1) * (Bn * Hn) + b * Hn + j], hh);
            enc_out[((size_t)b * Sn + t) * Hn + j] = (t < len_b) ? hh : 0.f;
        }
        grp_bar(bg, (unsigned)t);
    }
}

// ===========================================================================
// Decoder LSTM: one full barrier per step + early p-arrival counter.
// ===========================================================================
#define DEC_SMEM ((64 * W_PAD + 8 * H_PAD + 256 * RED_PAD + 4 * 516 + 64) * 4)
__global__ void __launch_bounds__(256, 1) lstm_dec_kernel(
    const float* __restrict__ ctxproj, const float* __restrict__ Whh,
    const float* __restrict__ Wih, const float* __restrict__ c0,
    const float* __restrict__ W_o1, const float* __restrict__ b_o1,
    const float* __restrict__ W_o2)
{
    extern __shared__ float sm[];
    float* w_s   = sm;                         // [64][W_PAD]
    float* h_s   = sm + 64 * W_PAD;            // [8][H_PAD]
    float* red_s = h_s + 8 * H_PAD;            // [256][RED_PAD]
    float* wo1_s = red_s + 256 * RED_PAD;      // [4][516]
    float* wp_s  = wo1_s + 4 * 516;            // [64]

    const int bg = blockIdx.x & 3, jg = blockIdx.x >> 2;
    const int tid = threadIdx.x;
    const int mj = tid & 15, mkc = tid >> 4;
    const int cb = tid >> 4, cj = tid & 15;
    const bool is_cons = (tid < 128);
    const int b = bg * 8 + cb;
    const int j = jg * 16 + cj;
    const int warp = tid >> 5, lane = tid & 31;

    for (int i = tid; i < 64 * 512; i += 256) {
        int lr = i >> 9, k = i & 511;
        w_s[lr * W_PAD + k] = Whh[(size_t)((lr >> 4) * Hn + jg * 16 + (lr & 15)) * Hn + k];
    }
    for (int i = tid; i < 4 * 512; i += 256) {
        int e = i >> 9, k = i & 511;
        wo1_s[e * 516 + k] = W_o1[(size_t)(jg * 4 + e) * Hn + k];
    }
    if (tid < 64) {
        wp_s[tid] = Wih[(size_t)((tid >> 4) * Hn + jg * 16 + (tid & 15)) * 513];
    }
    float wo2_r[4], bo1_r[4];
    #pragma unroll
    for (int e = 0; e < 4; ++e) { wo2_r[e] = W_o2[jg * 4 + e]; bo1_r[e] = b_o1[jg * 4 + e]; }
    float c_reg = is_cons ? c0[j] : 0.f;
    __syncthreads();

    const float* w0p = w_s + (0 * 16 + mj) * W_PAD + mkc * 32;
    const float* w1p = w_s + (1 * 16 + mj) * W_PAD + mkc * 32;
    const float* w2p = w_s + (2 * 16 + mj) * W_PAD + mkc * 32;
    const float* w3p = w_s + (3 * 16 + mj) * W_PAD + mkc * 32;
    const float* hb  = h_s + mkc * 32;

    for (int t = 0; t < Sn; ++t) {
        const float4* src = (const float4*)(g_h + (t & 1) * (Bn * Hn) + bg * 8 * Hn);
        #pragma unroll
        for (int i = 0; i < 4; ++i) {
            int idx = tid + i * 256;
            float4 v = __ldcg(src + idx);
            ((float4*)(h_s + (idx >> 7) * H_PAD))[idx & 127] = v;
        }
        float xp0 = 0.f, xp1 = 0.f, xp2 = 0.f, xp3 = 0.f;
        if (is_cons) {
            const float* xp = ctxproj + ((size_t)b * Sn + t) * Gn + j;
            xp0 = xp[0]; xp1 = xp[512]; xp2 = xp[1024]; xp3 = xp[1536];
        }
        __syncthreads();

        // output-MLP partials for p[t-1]; post arrival early
        if (t > 0) {
            float padd = 0.f;
            #pragma unroll
            for (int e = 0; e < 4; ++e) {
                float s = 0.f;
                #pragma unroll
                for (int kk = 0; kk < 16; ++kk) {
                    int k = kk * 32 + lane;
                    s += wo1_s[e * 516 + k] * h_s[warp * H_PAD + k];
                }
                #pragma unroll
                for (int o = 16; o; o >>= 1) s += __shfl_xor_sync(0xffffffffu, s, o);
                padd += fmaxf(s + bo1_r[e], 0.f) * wo2_r[e];
            }
            if (lane == 0)
                atomicAdd(&g_pred[(bg * 8 + warp) * Sn + (t - 1)], padd);
            __syncthreads();
            if (tid == 0) {
                unsigned v;
                asm volatile("atom.acq_rel.gpu.add.u32 %0, [%1], %2;"
                             : "=r"(v) : "l"(&g_pcnt[bg * 32]), "r"(1u) : "memory");
            }
        }

        unsigned long long acc[4][8];
        #pragma unroll
        for (int g = 0; g < 4; ++g)
            #pragma unroll
            for (int bb = 0; bb < 8; ++bb) acc[g][bb] = 0ull;

        #pragma unroll 4
        for (int it = 0; it < 16; ++it) {
            unsigned long long wv0 = *(const unsigned long long*)(w0p + it * 2);
            unsigned long long wv1 = *(const unsigned long long*)(w1p + it * 2);
            unsigned long long wv2 = *(const unsigned long long*)(w2p + it * 2);
            unsigned long long wv3 = *(const unsigned long long*)(w3p + it * 2);
            unsigned long long hv[8];
            #pragma unroll
            for (int bb = 0; bb < 8; ++bb)
                hv[bb] = *(const unsigned long long*)(hb + bb * H_PAD + it * 2);
            #pragma unroll
            for (int bb = 0; bb < 8; ++bb) {
                acc[0][bb] = fma2(wv0, hv[bb], acc[0][bb]);
                acc[1][bb] = fma2(wv1, hv[bb], acc[1][bb]);
                acc[2][bb] = fma2(wv2, hv[bb], acc[2][bb]);
                acc[3][bb] = fma2(wv3, hv[bb], acc[3][bb]);
            }
        }
        float* r = red_s + tid * RED_PAD;
        #pragma unroll
        for (int g = 0; g < 4; ++g)
            #pragma unroll
            for (int bb = 0; bb < 8; ++bb) {
                float2 u = unpack2(acc[g][bb]);
                r[g * 8 + bb] = u.x + u.y;
            }

        if (tid == 0 && t > 0) {
            unsigned rr;
            do {
                asm volatile("ld.acquire.gpu.u32 %0, [%1];"
                             : "=r"(rr) : "l"(&g_pcnt[bg * 32]) : "memory");
            } while (rr < 32u * (unsigned)t);
        }
        __syncthreads();

        if (is_cons) {
            float p_prev = (t > 0) ? __ldcg(&g_pred[b * Sn + (t - 1)]) : 0.f;
            float gi = xp0 + p_prev * wp_s[0 * 16 + cj];
            float gf = xp1 + p_prev * wp_s[1 * 16 + cj];
            float gg = xp2 + p_prev * wp_s[2 * 16 + cj];
            float go = xp3 + p_prev * wp_s[3 * 16 + cj];
            #pragma unroll
            for (int kc = 0; kc < 16; ++kc) {
                const float* rr = red_s + (kc * 16 + cj) * RED_PAD + cb;
                gi += rr[0]; gf += rr[8]; gg += rr[16]; go += rr[24];
            }
            float si = fast_sigmoid(gi), sf = fast_sigmoid(gf), so = fast_sigmoid(go);
            c_reg = sf * c_reg + si * fast_tanh(gg);
            float hh = so * fast_tanh(c_reg);
            __stcg(&g_h[((t + 1) & 1) * (Bn * Hn) + b * Hn + j], hh);
        }
        grp_bar(bg, (unsigned)t);
    }

    // final step's output MLP (t = Sn-1)
    {
        const float4* src = (const float4*)(g_h + (Sn & 1) * (Bn * Hn) + bg * 8 * Hn);
        #pragma unroll
        for (int i = 0; i < 4; ++i) {
            int idx = tid + i * 256;
            float4 v = __ldcg(src + idx);
            ((float4*)(h_s + (idx >> 7) * H_PAD))[idx & 127] = v;
        }
        __syncthreads();
        float padd = 0.f;
        #pragma unroll
        for (int e = 0; e < 4; ++e) {
            float s = 0.f;
            #pragma unroll
            for (int kk = 0; kk < 16; ++kk) {
                int k = kk * 32 + lane;
                s += wo1_s[e * 516 + k] * h_s[warp * H_PAD + k];
            }
            #pragma unroll
            for (int o = 16; o; o >>= 1) s += __shfl_xor_sync(0xffffffffu, s, o);
            padd += fmaxf(s + bo1_r[e], 0.f) * wo2_r[e];
        }
        if (lane == 0)
            atomicAdd(&g_pred[(bg * 8 + warp) * Sn + (Sn - 1)], padd);
    }
}

__global__ void finalize_kernel(const float* __restrict__ mask, float* __restrict__ out)
{
    int i = blockIdx.x * 256 + threadIdx.x;
    if (i < Mn) out[i] = g_pred[i] * mask[i];
}

extern "C" void kernel_launch(void* const* d_in, const int* in_sizes, int n_in,
                              void* d_out, int out_size)
{
    const float* inputs  = (const float*)d_in[0];
    const float* mask    = (const float*)d_in[1];
    const int*   lengths = (const int*)  d_in[2];
    const float* W_e     = (const float*)d_in[3];
    const float* b_e     = (const float*)d_in[4];
    const float* W_a1    = (const float*)d_in[5];
    const float* b_a1    = (const float*)d_in[6];
    const float* W_a2    = (const float*)d_in[7];
    const float* b_a2    = (const float*)d_in[8];
    const float* Wih_e   = (const float*)d_in[9];
    const float* Whh_e   = (const float*)d_in[10];
    const float* bih_e   = (const float*)d_in[11];
    const float* bhh_e   = (const float*)d_in[12];
    const float* enc_h0  = (const float*)d_in[13];
    const float* enc_c0  = (const float*)d_in[14];
    const float* Wih_d   = (const float*)d_in[15];
    const float* Whh_d   = (const float*)d_in[16];
    const float* bih_d   = (const float*)d_in[17];
    const float* bhh_d   = (const float*)d_in[18];
    const float* dec_h0  = (const float*)d_in[19];
    const float* dec_c0  = (const float*)d_in[20];
    const float* W_o1    = (const float*)d_in[21];
    const float* b_o1    = (const float*)d_in[22];
    const float* W_o2    = (const float*)d_in[23];
    const float* b_o2    = (const float*)d_in[24];
    float* out = (float*)d_out;

    float *p_embed, *p_a1, *p_a, *p_attn, *p_xproj, *p_enc, *p_ctx;
    cudaGetSymbolAddress((void**)&p_embed, g_embed);
    cudaGetSymbolAddress((void**)&p_a1,    g_a1);
    cudaGetSymbolAddress((void**)&p_a,     g_a);
    cudaGetSymbolAddress((void**)&p_attn,  g_attn);
    cudaGetSymbolAddress((void**)&p_xproj, g_xproj);
    cudaGetSymbolAddress((void**)&p_enc,   g_enc);
    cudaGetSymbolAddress((void**)&p_ctx,   g_ctx);

    cudaFuncSetAttribute(lstm_enc_kernel, cudaFuncAttributeMaxDynamicSharedMemorySize, ENC_SMEM);
    cudaFuncSetAttribute(lstm_dec_kernel, cudaFuncAttributeMaxDynamicSharedMemorySize, DEC_SMEM);

    sgemm_kernel<<<dim3(En / 128, Mn / 128), 256>>>(
        inputs, W_e, p_embed, Mn, En, 1024, 1024, 1024, 0, b_e, nullptr, 1);
    sgemm_kernel<<<dim3(En / 128, Mn / 128), 256>>>(
        p_embed, W_a1, p_a1, Mn, En, En, En, En, 0, b_a1, nullptr, 1);
    attn_logits_kernel<<<Mn / 8, 256>>>(p_a1, W_a2, b_a2, p_a);
    softmax_time_kernel<<<Bn * 3, 256>>>(p_a, p_attn);
    sgemm_kernel<<<dim3(Gn / 128, Mn / 128), 256>>>(
        p_embed, Wih_e, p_xproj, Mn, Gn, En, En, En, 0, bih_e, bhh_e, 0);
    init_enc_kernel<<<(Bn * Hn + 255) / 256, 256>>>(enc_h0);
    lstm_enc_kernel<<<NBG * NJG, 256, ENC_SMEM>>>(p_xproj, Whh_e, enc_c0, lengths, p_enc);
    context_kernel<<<Mn, Hn / 4>>>(p_attn, p_enc, p_ctx);
    sgemm_kernel<<<dim3(Gn / 128, Mn / 128), 256>>>(
        p_ctx, Wih_d, p_xproj, Mn, Gn, Hn, Hn, Hn + 1, 1, bih_d, bhh_d, 0);
    init_dec_kernel<<<(Mn + 255) / 256, 256>>>(dec_h0, b_o2);
    lstm_dec_kernel<<<NBG * NJG, 256, DEC_SMEM>>>(p_xproj, Whh_d, Wih_d, dec_c0, W_o1, b_o1, W_o2);
    finalize_kernel<<<(Mn + 255) / 256, 256>>>(mask, out);
}